// round 3
// baseline (speedup 1.0000x reference)
#include <cuda_runtime.h>
#include <cstdint>
#include <math.h>

#define NB   32
#define NC   256
#define NS   1024
#define NBS  (NB * NS)     // 32768
#define NCS  (NC * NS)     // 262144

// ---------------- device scratch (no allocations allowed) ----------------
__device__ float g_ink_b[NBS];                 // 1/||k_b column||
__device__ float g_inq [NBS];                  // 1/||q_grid column||
__device__ float g_inkg[NBS];                  // 1/||k_grid column||
__device__ float g_qgt[(size_t)NB * NS * NC];  // normalized q_grid, [B,S,C]
__device__ float g_kgt[(size_t)NB * NS * NC];  // normalized k_grid, [B,S,C]
__device__ unsigned long long g_arg[NBS];      // packed (value, ~j) argmax
__device__ int   g_negidx[NB];
__device__ float g_loss;

// ---------------- Kernel A: column norms + state reset ----------------
__global__ void norms_init_kernel(const float* __restrict__ kb,
                                  const float* __restrict__ qg,
                                  const float* __restrict__ kg) {
    int t = blockIdx.x * blockDim.x + threadIdx.x;   // 0..32767
    int b = t >> 10, s = t & 1023;
    const float* p1 = kb + b * NCS + s;
    const float* p2 = qg + b * NCS + s;
    const float* p3 = kg + b * NCS + s;
    float s1 = 0.f, s2 = 0.f, s3 = 0.f;
#pragma unroll 8
    for (int c = 0; c < NC; c++) {
        float v1 = p1[c * NS], v2 = p2[c * NS], v3 = p3[c * NS];
        s1 += v1 * v1; s2 += v2 * v2; s3 += v3 * v3;
    }
    g_ink_b[t] = 1.0f / fmaxf(sqrtf(s1), 1e-12f);
    g_inq [t]  = 1.0f / fmaxf(sqrtf(s2), 1e-12f);
    g_inkg[t]  = 1.0f / fmaxf(sqrtf(s3), 1e-12f);
    g_arg[t] = 0ull;                 // graph replays: must reset every call
    if (t == 0) g_loss = 0.0f;
}

// ---------------- Kernel B: normalize + transpose to [B,S,C] ----------------
__global__ void transpose_kernel(const float* __restrict__ qg,
                                 const float* __restrict__ kg) {
    __shared__ float tile[32][33];
    int z = blockIdx.z;              // 0..63: (b, tensor)
    int b = z >> 1;
    int tensor = z & 1;
    const float* in  = tensor ? kg     : qg;
    const float* inv = tensor ? g_inkg : g_inq;
    float*       out = tensor ? g_kgt  : g_qgt;
    int c0 = blockIdx.y * 32;
    int s0 = blockIdx.x * 32;
    int x = threadIdx.x, y = threadIdx.y;     // (32, 8)
#pragma unroll
    for (int cc = 0; cc < 32; cc += 8)
        tile[y + cc][x] = in[(size_t)b * NCS + (size_t)(c0 + y + cc) * NS + s0 + x];
    __syncthreads();
#pragma unroll
    for (int cc = 0; cc < 32; cc += 8) {
        int s = s0 + y + cc;
        out[((size_t)b * NS + s) * NC + c0 + x] = tile[x][y + cc] * inv[b * NS + s];
    }
}

// ---------------- Kernel C: fused SGEMM (f32x2) + scaled argmax ----------------
// sim[b][i][j] = sum_c q_b[b][c][i] * k_b[b][c][j];   argmax_j (sim * ink_b[j])
// Packed fp32 FMA (fma.rn.f32x2, sm_103a) — bitwise identical to scalar FFMA.
__device__ __forceinline__ unsigned long long pack_key(float v, int j) {
    unsigned int u = __float_as_uint(v);
    u = (u & 0x80000000u) ? ~u : (u | 0x80000000u);     // order-preserving
    return ((unsigned long long)u << 32) | (unsigned int)(0xFFFFFFFFu - (unsigned int)j);
}

__device__ __forceinline__ unsigned long long dup_f32(float x) {
    unsigned long long r;
    asm("mov.b64 %0, {%1, %1};" : "=l"(r) : "f"(x));
    return r;
}
__device__ __forceinline__ void ffma2(unsigned long long& d,
                                      unsigned long long a,
                                      unsigned long long b) {
    asm("fma.rn.f32x2 %0, %1, %2, %0;" : "+l"(d) : "l"(a), "l"(b));
}
__device__ __forceinline__ void unpack2(unsigned long long v, float& lo, float& hi) {
    asm("mov.b64 {%0, %1}, %2;" : "=f"(lo), "=f"(hi) : "l"(v));
}

__global__ __launch_bounds__(256, 2)
void gemm_argmax_kernel(const float* __restrict__ qb, const float* __restrict__ kb) {
    __shared__ float As[2][16][128];
    __shared__ float Bs[2][16][128];
    int b  = blockIdx.z;
    int i0 = blockIdx.y * 128;
    int j0 = blockIdx.x * 128;
    const float* Q = qb + (size_t)b * NCS;
    const float* K = kb + (size_t)b * NCS;
    int tid = threadIdx.x;
    int tx = tid & 15, ty = tid >> 4;

    // per-thread gmem source coords (same for every k-tile)
    int r0 = tid >> 5,         c0 = (tid & 31) << 2;         // vec 0
    int r1 = (tid + 256) >> 5, c1 = ((tid + 256) & 31) << 2; // vec 1

    unsigned long long acc2[8][4];
#pragma unroll
    for (int r = 0; r < 8; r++)
#pragma unroll
        for (int c = 0; c < 4; c++) acc2[r][c] = 0ull;

    // preload k-tile 0
    {
        *(float4*)&As[0][r0][c0] = *(const float4*)(Q + (size_t)r0 * NS + i0 + c0);
        *(float4*)&As[0][r1][c1] = *(const float4*)(Q + (size_t)r1 * NS + i0 + c1);
        *(float4*)&Bs[0][r0][c0] = *(const float4*)(K + (size_t)r0 * NS + j0 + c0);
        *(float4*)&Bs[0][r1][c1] = *(const float4*)(K + (size_t)r1 * NS + j0 + c1);
    }
    __syncthreads();

    int buf = 0;
    for (int kc = 0; kc < NC; kc += 16) {
        float4 pa0, pa1, pb0, pb1;
        bool has_next = (kc + 16) < NC;
        if (has_next) {   // prefetch next k-tile into registers
            const float* Qn = Q + (size_t)(kc + 16) * NS + i0;
            const float* Kn = K + (size_t)(kc + 16) * NS + j0;
            pa0 = *(const float4*)(Qn + (size_t)r0 * NS + c0);
            pa1 = *(const float4*)(Qn + (size_t)r1 * NS + c1);
            pb0 = *(const float4*)(Kn + (size_t)r0 * NS + c0);
            pb1 = *(const float4*)(Kn + (size_t)r1 * NS + c1);
        }
#pragma unroll
        for (int k = 0; k < 16; k++) {
            float4 a0 = *(const float4*)&As[buf][k][ty * 4];
            float4 a1 = *(const float4*)&As[buf][k][64 + ty * 4];
            ulonglong2 b0 = *(const ulonglong2*)&Bs[buf][k][tx * 4];
            ulonglong2 b1 = *(const ulonglong2*)&Bs[buf][k][64 + tx * 4];
            unsigned long long bbv[4] = {b0.x, b0.y, b1.x, b1.y};
            float av[8] = {a0.x, a0.y, a0.z, a0.w, a1.x, a1.y, a1.z, a1.w};
#pragma unroll
            for (int r = 0; r < 8; r++) {
                unsigned long long a2 = dup_f32(av[r]);
#pragma unroll
                for (int c = 0; c < 4; c++) ffma2(acc2[r][c], a2, bbv[c]);
            }
        }
        if (has_next) {
            int nb = buf ^ 1;
            *(float4*)&As[nb][r0][c0] = pa0;
            *(float4*)&As[nb][r1][c1] = pa1;
            *(float4*)&Bs[nb][r0][c0] = pb0;
            *(float4*)&Bs[nb][r1][c1] = pb1;
            __syncthreads();
            buf = nb;
        }
    }

    // epilogue: scale cols by 1/||k_b[j]||, argmax per row (first-max ties)
    float inkv[8];
#pragma unroll
    for (int cc = 0; cc < 8; cc++) {
        int col = (cc < 4) ? (tx * 4 + cc) : (64 + tx * 4 + cc - 4);
        inkv[cc] = g_ink_b[b * NS + j0 + col];
    }
#pragma unroll
    for (int rr = 0; rr < 8; rr++) {
        float best = -3.4e38f; int bj = 0;
#pragma unroll
        for (int c2 = 0; c2 < 4; c2++) {      // cols ascend -> first-max kept
            float lo, hi;
            unpack2(acc2[rr][c2], lo, hi);
            int cc = c2 * 2;                  // 0,2 | 4,6 within inkv ordering
            int colL = (c2 < 2) ? (tx * 4 + 2 * c2) : (64 + tx * 4 + 2 * (c2 - 2));
            float vL = lo * inkv[cc];
            float vH = hi * inkv[cc + 1];
            if (vL > best) { best = vL; bj = j0 + colL; }
            if (vH > best) { best = vH; bj = j0 + colL + 1; }
        }
        unsigned long long key = pack_key(best, bj);
#pragma unroll
        for (int off = 8; off; off >>= 1) {   // 16-lane groups share a row
            unsigned long long o = __shfl_xor_sync(0xFFFFFFFFu, key, off);
            if (o > key) key = o;
        }
        if (tx == 0) {
            int row = (rr < 4) ? (ty * 4 + rr) : (64 + ty * 4 + rr - 4);
            atomicMax(&g_arg[b * NS + i0 + row], key);
        }
    }
}

// ---------------- Kernel D: jax PARTITIONABLE threefry -> uniform -> neg_idx -
__device__ __forceinline__ void threefry2x32(uint32_t k0, uint32_t k1,
                                             uint32_t x0, uint32_t x1,
                                             uint32_t& o0, uint32_t& o1) {
    uint32_t ks0 = k0, ks1 = k1, ks2 = k0 ^ k1 ^ 0x1BD11BDAu;
    const int r0[4] = {13, 15, 26, 6};
    const int r1[4] = {17, 29, 16, 24};
    x0 += ks0; x1 += ks1;
    uint32_t ks[3] = {ks0, ks1, ks2};
#pragma unroll
    for (int i = 0; i < 5; i++) {
        const int* rr = (i & 1) ? r1 : r0;
#pragma unroll
        for (int j = 0; j < 4; j++) {
            x0 += x1;
            x1 = (x1 << rr[j]) | (x1 >> (32 - rr[j]));
            x1 ^= x0;
        }
        x0 += ks[(i + 1) % 3];
        x1 += ks[(i + 2) % 3] + (uint32_t)(i + 1);
    }
    o0 = x0; o1 = x1;
}

__global__ void negidx_kernel(const int* __restrict__ labels_raw) {
    __shared__ float uf[1024];
    __shared__ int lab[32];
    __shared__ int is64;
    int t = threadIdx.x;   // 1024 threads, one per element of u (32x32)
    uint32_t o0, o1;
    threefry2x32(0u, 42u, 0u, (uint32_t)t, o0, o1);   // counter = (hi=0, lo=n)
    uint32_t bits = o0 ^ o1;                           // partitionable fold
    uf[t] = __uint_as_float((bits >> 9) | 0x3f800000u) - 1.0f;
    if (t == 0) {
        // int64 little-endian with small labels => every odd int32 word is 0
        int all0 = 1;
        for (int i = 1; i < 32; i += 2) all0 &= (labels_raw[i] == 0);
        is64 = all0;
    }
    __syncthreads();
    if (t < 32) lab[t] = is64 ? labels_raw[2 * t] : labels_raw[t];
    __syncthreads();
    if (t < 32) {
        int lb = lab[t];
        float best = -2.0f; int bi = 0;
        for (int j = 0; j < 32; j++) {
            float v = (lab[j] != lb) ? uf[t * 32 + j] : -1.0f;
            if (v > best) { best = v; bi = j; }    // first-max ties
        }
        g_negidx[t] = bi;
    }
}

// ---------------- Kernel E: loss terms (warp per (b,i)) ----------------
__global__ void loss_kernel() {
    __shared__ float part[8];
    int wid = threadIdx.x >> 5, lane = threadIdx.x & 31;
    int gw = blockIdx.x * 8 + wid;          // 0..32767
    int b = gw >> 10, i = gw & 1023;
    unsigned long long key = g_arg[gw];
    int idx = (int)(0xFFFFFFFFu - (unsigned int)(key & 0xFFFFFFFFull));
    int nb = g_negidx[b];
    const float4* q  = (const float4*)(g_qgt + (size_t)gw * NC);
    const float4* kp = (const float4*)(g_kgt + ((size_t)b  * NS + idx) * NC);
    const float4* kn = (const float4*)(g_kgt + ((size_t)nb * NS + i)   * NC);
    float dp = 0.f, dn = 0.f;
#pragma unroll
    for (int u = 0; u < 2; u++) {
        int c4 = lane + u * 32;
        float4 qv = q[c4], pv = kp[c4], nv = kn[c4];
        dp += qv.x * pv.x + qv.y * pv.y + qv.z * pv.z + qv.w * pv.w;
        dn += qv.x * nv.x + qv.y * nv.y + qv.z * nv.z + qv.w * nv.w;
    }
#pragma unroll
    for (int off = 16; off; off >>= 1) {
        dp += __shfl_xor_sync(0xFFFFFFFFu, dp, off);
        dn += __shfl_xor_sync(0xFFFFFFFFu, dn, off);
    }
    if (lane == 0) {
        float p = dp * 10.0f;   // / TEMP
        float n = dn * 10.0f;
        part[wid] = logf(expf(p) + expf(n) + 1e-6f) - p;
    }
    __syncthreads();
    if (threadIdx.x == 0) {
        float s = 0.f;
        for (int w = 0; w < 8; w++) s += part[w];
        atomicAdd(&g_loss, s);
    }
}

__global__ void finalize_kernel(float* out) {
    out[0] = g_loss * (1.0f / 32768.0f);   // mean * LAM(=1)
}

// ---------------- entry ----------------
extern "C" void kernel_launch(void* const* d_in, const int* in_sizes, int n_in,
                              void* d_out, int out_size) {
    const float* q_b    = (const float*)d_in[0];
    const float* k_b    = (const float*)d_in[1];
    const float* q_grid = (const float*)d_in[2];
    const float* k_grid = (const float*)d_in[3];
    const int*   labels = (const int*)d_in[4];

    norms_init_kernel<<<128, 256>>>(k_b, q_grid, k_grid);
    transpose_kernel<<<dim3(32, 8, 64), dim3(32, 8)>>>(q_grid, k_grid);
    negidx_kernel<<<1, 1024>>>(labels);
    gemm_argmax_kernel<<<dim3(8, 8, 32), 256>>>(q_b, k_b);
    loss_kernel<<<4096, 256>>>();
    finalize_kernel<<<1, 1>>>((float*)d_out);
}

// round 8
// speedup vs baseline: 2.7265x; 2.7265x over previous
#include <cuda_runtime.h>
#include <cuda_bf16.h>
#include <cstdint>
#include <math.h>

#define NB   32
#define NC   256
#define NS   1024
#define NBS  (NB * NS)     // 32768
#define NCS  (NC * NS)     // 262144

// tcgen05 exists only on arch-specific (a) targets; the harness also compiles
// a compute_103 (non-a) pass, which must still build AND be correct.
#if defined(__CUDA_ARCH__) && (defined(__CUDA_ARCH_FEAT_SM103_ALL) || defined(__CUDA_ARCH_FEAT_SM100_ALL) || defined(__CUDA_ARCH_FEAT_SM101_ALL))
#define HAS_TCGEN05 1
#else
#define HAS_TCGEN05 0
#endif

// ---------------- device scratch (no allocations allowed) ----------------
__device__ float g_ink_b[NBS];                 // 1/||k_b column||
__device__ float g_inq [NBS];                  // 1/||q_grid column||
__device__ float g_inkg[NBS];                  // 1/||k_grid column||
__device__ float g_qgt[(size_t)NB * NS * NC];  // normalized q_grid, [B,S,C]
__device__ float g_kgt[(size_t)NB * NS * NC];  // normalized k_grid, [B,S,C]
__device__ __nv_bfloat16 g_qbt_hi[(size_t)NB * NS * NC];  // raw q_b, [B,S,C]
__device__ __nv_bfloat16 g_qbt_lo[(size_t)NB * NS * NC];
__device__ __nv_bfloat16 g_kbt_hi[(size_t)NB * NS * NC];  // normalized k_b
__device__ __nv_bfloat16 g_kbt_lo[(size_t)NB * NS * NC];
__device__ unsigned long long g_arg[NBS];      // packed (value, ~j) argmax
__device__ int   g_negidx[NB];
__device__ float g_loss;

// ---------------- PTX helpers ----------------
__device__ __forceinline__ uint32_t smem_u32(const void* p) {
    uint32_t a;
    asm("{ .reg .u64 t; cvta.to.shared.u64 t, %1; cvt.u32.u64 %0, t; }"
        : "=r"(a) : "l"(p));
    return a;
}

#if HAS_TCGEN05
__device__ __forceinline__ uint32_t elect_one_pred() {
    uint32_t pred;
    asm volatile("{\n\t.reg .pred p;\n\telect.sync _|p, 0xFFFFFFFF;\n\t"
                 "selp.b32 %0, 1, 0, p;\n\t}" : "=r"(pred));
    return pred;
}
#define TCGEN05_ALLOC(smem_addr, nCols) \
    asm volatile("tcgen05.alloc.cta_group::1.sync.aligned.shared::cta.b32 [%0], %1;" \
        :: "r"((uint32_t)(smem_addr)), "r"((uint32_t)(nCols)) : "memory")
#define TCGEN05_DEALLOC(tmem, nCols) \
    asm volatile("tcgen05.dealloc.cta_group::1.sync.aligned.b32 %0, %1;" \
        :: "r"(tmem), "r"((uint32_t)(nCols)))
#define TCGEN05_RELINQ() \
    asm volatile("tcgen05.relinquish_alloc_permit.cta_group::1.sync.aligned;")
#define TCGEN05_WAIT_LD() asm volatile("tcgen05.wait::ld.sync.aligned;" ::: "memory")
#define TCGEN05_WAIT_ST() asm volatile("tcgen05.wait::st.sync.aligned;" ::: "memory")
#define TCGEN05_FENCE_BEFORE() asm volatile("tcgen05.fence::before_thread_sync;" ::: "memory")
#define TCGEN05_FENCE_AFTER()  asm volatile("tcgen05.fence::after_thread_sync;" ::: "memory")
#define TCGEN05_COMMIT(mbar) \
    asm volatile("tcgen05.commit.cta_group::1.mbarrier::arrive::one.shared::cluster.b64 [%0];" \
        :: "r"((uint32_t)(mbar)) : "memory")
#define FENCE_ASYNC() asm volatile("fence.proxy.async.shared::cta;" ::: "memory")
#define MBARRIER_INIT(mbar, cnt) \
    asm volatile("mbarrier.init.shared.b64 [%0], %1;" \
        :: "r"((uint32_t)(mbar)), "r"((uint32_t)(cnt)) : "memory")
#define MBARRIER_WAIT_PARITY(mbar, par) do { \
    uint32_t _m = (uint32_t)(mbar); uint32_t _p = (uint32_t)(par); uint32_t _d; \
    asm volatile("{\n\t.reg .pred p;\n\t" \
        "mbarrier.try_wait.parity.acquire.cta.shared::cta.b64 p, [%1], %2;\n\t" \
        "selp.b32 %0, 1, 0, p;\n\t}" : "=r"(_d) : "r"(_m), "r"(_p) : "memory"); \
    if (!_d) { \
        asm volatile("{\n\t.reg .pred P1;\n\t" \
            "WL_%=:\n\t" \
            "mbarrier.try_wait.parity.acquire.cta.shared::cta.b64 P1, [%0], %1, 0x989680;\n\t" \
            "@P1 bra.uni WD_%=;\n\tbra.uni WL_%=;\n\tWD_%=:\n\t}" \
            :: "r"(_m), "r"(_p) : "memory"); \
    } } while(0)

// TS-mode bf16 MMA: D(TMEM) += A(TMEM) * B(SMEM desc)^T
__device__ __forceinline__ void mma_f16_ts(uint32_t d_tmem, uint32_t a_tmem,
                                           uint64_t b_desc, uint32_t idesc,
                                           uint32_t enable) {
    asm volatile("{\n\t.reg .pred p;\n\tsetp.ne.u32 p, %4, 0;\n\t"
        "tcgen05.mma.cta_group::1.kind::f16 [%0], [%1], %2, %3, {%5,%5,%5,%5}, p;\n\t}"
        :: "r"(d_tmem), "r"(a_tmem), "l"(b_desc), "r"(idesc), "r"(enable), "r"(0u)
        : "memory");
}
#define TCGEN05_ST_X64(tmem, r) \
    asm volatile("tcgen05.st.sync.aligned.32x32b.x64.b32 [%0], " \
        "{%1,%2,%3,%4,%5,%6,%7,%8,%9,%10,%11,%12,%13,%14,%15,%16," \
        "%17,%18,%19,%20,%21,%22,%23,%24,%25,%26,%27,%28,%29,%30,%31,%32," \
        "%33,%34,%35,%36,%37,%38,%39,%40,%41,%42,%43,%44,%45,%46,%47,%48," \
        "%49,%50,%51,%52,%53,%54,%55,%56,%57,%58,%59,%60,%61,%62,%63,%64};" \
        :: "r"(tmem), \
        "r"((r)[0]),"r"((r)[1]),"r"((r)[2]),"r"((r)[3]),"r"((r)[4]),"r"((r)[5]),"r"((r)[6]),"r"((r)[7]), \
        "r"((r)[8]),"r"((r)[9]),"r"((r)[10]),"r"((r)[11]),"r"((r)[12]),"r"((r)[13]),"r"((r)[14]),"r"((r)[15]), \
        "r"((r)[16]),"r"((r)[17]),"r"((r)[18]),"r"((r)[19]),"r"((r)[20]),"r"((r)[21]),"r"((r)[22]),"r"((r)[23]), \
        "r"((r)[24]),"r"((r)[25]),"r"((r)[26]),"r"((r)[27]),"r"((r)[28]),"r"((r)[29]),"r"((r)[30]),"r"((r)[31]), \
        "r"((r)[32]),"r"((r)[33]),"r"((r)[34]),"r"((r)[35]),"r"((r)[36]),"r"((r)[37]),"r"((r)[38]),"r"((r)[39]), \
        "r"((r)[40]),"r"((r)[41]),"r"((r)[42]),"r"((r)[43]),"r"((r)[44]),"r"((r)[45]),"r"((r)[46]),"r"((r)[47]), \
        "r"((r)[48]),"r"((r)[49]),"r"((r)[50]),"r"((r)[51]),"r"((r)[52]),"r"((r)[53]),"r"((r)[54]),"r"((r)[55]), \
        "r"((r)[56]),"r"((r)[57]),"r"((r)[58]),"r"((r)[59]),"r"((r)[60]),"r"((r)[61]),"r"((r)[62]),"r"((r)[63]) \
        : "memory")
#define TCGEN05_LD_X32(r, tmem) \
    asm volatile("tcgen05.ld.sync.aligned.32x32b.x32.b32 " \
        "{%0,%1,%2,%3,%4,%5,%6,%7,%8,%9,%10,%11,%12,%13,%14,%15," \
        "%16,%17,%18,%19,%20,%21,%22,%23,%24,%25,%26,%27,%28,%29,%30,%31}, [%32];" \
        : "=r"((r)[0]),"=r"((r)[1]),"=r"((r)[2]),"=r"((r)[3]),"=r"((r)[4]),"=r"((r)[5]),"=r"((r)[6]),"=r"((r)[7]), \
          "=r"((r)[8]),"=r"((r)[9]),"=r"((r)[10]),"=r"((r)[11]),"=r"((r)[12]),"=r"((r)[13]),"=r"((r)[14]),"=r"((r)[15]), \
          "=r"((r)[16]),"=r"((r)[17]),"=r"((r)[18]),"=r"((r)[19]),"=r"((r)[20]),"=r"((r)[21]),"=r"((r)[22]),"=r"((r)[23]), \
          "=r"((r)[24]),"=r"((r)[25]),"=r"((r)[26]),"=r"((r)[27]),"=r"((r)[28]),"=r"((r)[29]),"=r"((r)[30]),"=r"((r)[31]) \
        : "r"(tmem))

static constexpr uint64_t SMEM_DESC_BASE_SW128 =
    (uint64_t(2) << 61) | (uint64_t(1) << 46) | (uint64_t(64) << 32) | (uint64_t(1) << 16);
#define MAKE_SMEM_DESC(a) (SMEM_DESC_BASE_SW128 | ((uint64_t)((a) >> 4) & 0x3FFF))
#define SW128(off) ((off) ^ (((off) >> 3) & 0x70))
// idesc: f32 accum, bf16 a/b, N=64, M=128
#define MMA_IDESC 0x8100490u
#endif  // HAS_TCGEN05

// ---------------- Kernel A: column norms + state reset ----------------
__global__ void norms_init_kernel(const float* __restrict__ kb,
                                  const float* __restrict__ qg,
                                  const float* __restrict__ kg) {
    int t = blockIdx.x * blockDim.x + threadIdx.x;   // 0..32767
    int b = t >> 10, s = t & 1023;
    const float* p1 = kb + b * NCS + s;
    const float* p2 = qg + b * NCS + s;
    const float* p3 = kg + b * NCS + s;
    float s1 = 0.f, s2 = 0.f, s3 = 0.f;
#pragma unroll 8
    for (int c = 0; c < NC; c++) {
        float v1 = p1[c * NS], v2 = p2[c * NS], v3 = p3[c * NS];
        s1 += v1 * v1; s2 += v2 * v2; s3 += v3 * v3;
    }
    g_ink_b[t] = 1.0f / fmaxf(sqrtf(s1), 1e-12f);
    g_inq [t]  = 1.0f / fmaxf(sqrtf(s2), 1e-12f);
    g_inkg[t]  = 1.0f / fmaxf(sqrtf(s3), 1e-12f);
    g_arg[t] = 0ull;                 // graph replays: must reset every call
    if (t == 0) g_loss = 0.0f;
}

// ---------------- Kernel B: normalize + transpose ----------------
// t=0: q_grid -> g_qgt (float, *inq)   t=1: k_grid -> g_kgt (float, *inkg)
// t=2: q_b    -> g_qbt hi/lo (raw)     t=3: k_b    -> g_kbt hi/lo (*ink_b)
__global__ void transpose_kernel(const float* __restrict__ qg,
                                 const float* __restrict__ kg,
                                 const float* __restrict__ qb,
                                 const float* __restrict__ kb) {
    __shared__ float tile[32][33];
    int z = blockIdx.z;              // b*4 + t
    int b = z >> 2;
    int t = z & 3;
    const float* in = (t == 0) ? qg : (t == 1) ? kg : (t == 2) ? qb : kb;
    int c0 = blockIdx.y * 32;
    int s0 = blockIdx.x * 32;
    int x = threadIdx.x, y = threadIdx.y;     // (32, 8)
#pragma unroll
    for (int cc = 0; cc < 32; cc += 8)
        tile[y + cc][x] = in[(size_t)b * NCS + (size_t)(c0 + y + cc) * NS + s0 + x];
    __syncthreads();
#pragma unroll
    for (int cc = 0; cc < 32; cc += 8) {
        int s = s0 + y + cc;
        float v = tile[x][y + cc];
        size_t o = ((size_t)b * NS + s) * NC + c0 + x;
        if (t == 0) {
            g_qgt[o] = v * g_inq[b * NS + s];
        } else if (t == 1) {
            g_kgt[o] = v * g_inkg[b * NS + s];
        } else {
            if (t == 3) v *= g_ink_b[b * NS + s];
            __nv_bfloat16 hi = __float2bfloat16_rn(v);
            __nv_bfloat16 lo = __float2bfloat16_rn(v - __bfloat162float(hi));
            if (t == 2) { g_qbt_hi[o] = hi; g_qbt_lo[o] = lo; }
            else        { g_kbt_hi[o] = hi; g_kbt_lo[o] = lo; }
        }
    }
}

// ---------------- Kernel C: GEMM + argmax (tcgen05 or fallback) -----------
__device__ __forceinline__ unsigned long long pack_key(float v, int j) {
    unsigned int u = __float_as_uint(v);
    u = (u & 0x80000000u) ? ~u : (u | 0x80000000u);     // order-preserving
    return ((unsigned long long)u << 32) | (unsigned int)(0xFFFFFFFFu - (unsigned int)j);
}

// SMEM (dynamic, 1024-aligned): B_HI[2]@{0,64K}, B_LO[2]@{32K,96K}, ctrl@128K
// Fallback path reuses the same dynamic region differently.
#define SM_BHI(buf) ((buf) ? 65536 : 0)
#define SM_BLO(buf) ((buf) ? 98304 : 32768)
#define SM_PTR  131072
#define SM_MBAR 131080
#define SMEM_SZ (136 * 1024)

__global__ __launch_bounds__(128, 1)
void mma_argmax_kernel() {
    extern __shared__ char dsm_raw[];
    uint32_t sm0 = smem_u32(dsm_raw);
    uint32_t smb = (sm0 + 1023) & ~1023u;       // 1024-aligned base
    char* base = dsm_raw + (smb - sm0);

    int tid = threadIdx.x;                       // 128 threads
    int wid = tid >> 5, lane = tid & 31;
    int jh = blockIdx.x;                         // j half: 0/1
    int i0 = blockIdx.y * 128;
    int b  = blockIdx.z;

#if HAS_TCGEN05
    if (wid == 0) TCGEN05_ALLOC(smb + SM_PTR, 512);
    if (tid == 0) MBARRIER_INIT(smb + SM_MBAR, 1);
    __syncthreads();
    uint32_t tmem;
    asm volatile("ld.shared.b32 %0, [%1];" : "=r"(tmem) : "r"(smb + SM_PTR));
    uint32_t tA_hi = tmem;            // A hi: cols 0..127
    uint32_t tA_lo = tmem + 128;      // A lo: cols 128..255
    uint32_t tD    = tmem + 256;      // D:    cols 256..319

    // ---- A (q tile, 128 rows x 256 bf16) -> TMEM, hi then lo ----
    {
        uint32_t wo = (uint32_t)(wid) << 21;     // ST subpartition offset
        size_t rowoff = ((size_t)b * NS + i0 + tid) * NC;  // bf16 elements
        const uint4* srcs[2] = { (const uint4*)(g_qbt_hi + rowoff),
                                 (const uint4*)(g_qbt_lo + rowoff) };
        uint32_t tdst[2] = { tA_hi, tA_lo };
#pragma unroll
        for (int p = 0; p < 2; p++) {
#pragma unroll
            for (int half = 0; half < 2; half++) {
                uint32_t r[64];
#pragma unroll
                for (int q = 0; q < 16; q++) {
                    uint4 v = srcs[p][half * 16 + q];
                    r[q * 4 + 0] = v.x; r[q * 4 + 1] = v.y;
                    r[q * 4 + 2] = v.z; r[q * 4 + 3] = v.w;
                }
                TCGEN05_ST_X64(tdst[p] + half * 64 + wo, r);
            }
        }
        TCGEN05_WAIT_ST();
    }
    TCGEN05_FENCE_BEFORE();
    __syncthreads();

    // ---- B loader: 64 rows x 512B, SW128 blocked atoms (8 atom-rows) ----
    auto load_B = [&](int chunk, int buf) {
        int jb = jh * 512 + chunk * 64;
        const char* sh = (const char*)(g_kbt_hi + ((size_t)b * NS + jb) * NC);
        const char* sl = (const char*)(g_kbt_lo + ((size_t)b * NS + jb) * NC);
        char* dh = base + SM_BHI(buf);
        char* dl = base + SM_BLO(buf);
#pragma unroll
        for (int it = 0; it < 16; it++) {        // 2048 16B-chunks / 128 thr
            int idx = tid + it * 128;
            int row = idx >> 5;
            int cb  = (idx & 31) * 16;
            uint32_t off = (uint32_t)(((row >> 3) + (cb >> 7) * 8) * 1024
                                      + (row & 7) * 128 + (cb & 127));
            uint32_t sw = SW128(off);
            *(uint4*)(dh + sw) = *(const uint4*)(sh + (size_t)row * 512 + cb);
            *(uint4*)(dl + sw) = *(const uint4*)(sl + (size_t)row * 512 + cb);
        }
    };

    load_B(0, 0);
    __syncthreads();
    FENCE_ASYNC();

    float best = -3.4e38f;
    int   bj   = 0;
    int   jrow_base = jh * 512;

    for (int c = 0; c < 8; c++) {
        int buf = c & 1;
        if (wid == 0) {
            TCGEN05_FENCE_AFTER();
            if (elect_one_pred()) {
                uint64_t bh = MAKE_SMEM_DESC(smb + SM_BHI(buf));
                uint64_t bl = MAKE_SMEM_DESC(smb + SM_BLO(buf));
#pragma unroll
                for (int ks = 0; ks < 16; ks++) {
                    uint32_t aoff = ks * 8;
                    uint64_t boff = (uint64_t)((ks >> 2) * 512 + (ks & 3) * 2);
                    mma_f16_ts(tD, tA_hi + aoff, bh + boff, MMA_IDESC, ks != 0);
                    mma_f16_ts(tD, tA_hi + aoff, bl + boff, MMA_IDESC, 1u);
                    mma_f16_ts(tD, tA_lo + aoff, bh + boff, MMA_IDESC, 1u);
                }
                TCGEN05_COMMIT(smb + SM_MBAR);
            }
        }
        if (c < 7) load_B(c + 1, buf ^ 1);       // overlap with MMA

        MBARRIER_WAIT_PARITY(smb + SM_MBAR, c & 1);
        TCGEN05_FENCE_AFTER();
#pragma unroll
        for (int g = 0; g < 2; g++) {
            uint32_t regs[32];
            TCGEN05_LD_X32(regs, tD + g * 32);
            TCGEN05_WAIT_LD();
            int j0 = jrow_base + c * 64 + g * 32;
#pragma unroll
            for (int cc = 0; cc < 32; cc++) {    // ascending j -> first-max kept
                float v = __uint_as_float(regs[cc]);
                if (v > best) { best = v; bj = j0 + cc; }
            }
        }
        TCGEN05_FENCE_BEFORE();
        __syncthreads();                          // D free + B(c+1) stores done
        FENCE_ASYNC();
    }

    int row = i0 + wid * 32 + lane;
    atomicMax(&g_arg[b * NS + row], pack_key(best, bj));

    __syncthreads();
    if (wid == 0) { TCGEN05_RELINQ(); TCGEN05_DEALLOC(tmem, 512); }
#else
    // ---------- fallback (non-a target): smem-cached dot products ----------
    // A: 128 rows x 257 floats (padded, conflict-free); k row broadcast buffer.
    float* As = (float*)base;                    // 128*257*4 = 131584 B
    float* kv = As + 128 * 257;                  // 256 floats
    {
        size_t rowoff = ((size_t)b * NS + i0 + tid) * NC;
        const __nv_bfloat16* h = g_qbt_hi + rowoff;
        const __nv_bfloat16* l = g_qbt_lo + rowoff;
#pragma unroll 8
        for (int c = 0; c < NC; c++)
            As[tid * 257 + c] = __bfloat162float(h[c]) + __bfloat162float(l[c]);
    }
    __syncthreads();

    float best = -3.4e38f;
    int   bj   = 0;
    for (int j = 0; j < 512; j++) {
        int jr = jh * 512 + j;
        size_t ko = ((size_t)b * NS + jr) * NC;
        __syncthreads();                          // protect kv from prev iter
        kv[2 * tid]     = __bfloat162float(g_kbt_hi[ko + 2 * tid])
                        + __bfloat162float(g_kbt_lo[ko + 2 * tid]);
        kv[2 * tid + 1] = __bfloat162float(g_kbt_hi[ko + 2 * tid + 1])
                        + __bfloat162float(g_kbt_lo[ko + 2 * tid + 1]);
        __syncthreads();
        float dot = 0.f;
#pragma unroll 8
        for (int c = 0; c < NC; c++) dot += As[tid * 257 + c] * kv[c];
        if (dot > best) { best = dot; bj = jr; }  // ascending j -> first max
    }
    atomicMax(&g_arg[b * NS + i0 + tid], pack_key(best, bj));
    (void)wid; (void)lane;
#endif
}

// ---------------- Kernel D: jax PARTITIONABLE threefry -> uniform -> neg_idx -
__device__ __forceinline__ void threefry2x32(uint32_t k0, uint32_t k1,
                                             uint32_t x0, uint32_t x1,
                                             uint32_t& o0, uint32_t& o1) {
    uint32_t ks0 = k0, ks1 = k1, ks2 = k0 ^ k1 ^ 0x1BD11BDAu;
    const int r0[4] = {13, 15, 26, 6};
    const int r1[4] = {17, 29, 16, 24};
    x0 += ks0; x1 += ks1;
    uint32_t ks[3] = {ks0, ks1, ks2};
#pragma unroll
    for (int i = 0; i < 5; i++) {
        const int* rr = (i & 1) ? r1 : r0;
#pragma unroll
        for (int j = 0; j < 4; j++) {
            x0 += x1;
            x1 = (x1 << rr[j]) | (x1 >> (32 - rr[j]));
            x1 ^= x0;
        }
        x0 += ks[(i + 1) % 3];
        x1 += ks[(i + 2) % 3] + (uint32_t)(i + 1);
    }
    o0 = x0; o1 = x1;
}

__global__ void negidx_kernel(const int* __restrict__ labels_raw) {
    __shared__ float uf[1024];
    __shared__ int lab[32];
    __shared__ int is64;
    int t = threadIdx.x;   // 1024 threads, one per element of u (32x32)
    uint32_t o0, o1;
    threefry2x32(0u, 42u, 0u, (uint32_t)t, o0, o1);   // counter = (hi=0, lo=n)
    uint32_t bits = o0 ^ o1;                           // partitionable fold
    uf[t] = __uint_as_float((bits >> 9) | 0x3f800000u) - 1.0f;
    if (t == 0) {
        int all0 = 1;
        for (int i = 1; i < 32; i += 2) all0 &= (labels_raw[i] == 0);
        is64 = all0;
    }
    __syncthreads();
    if (t < 32) lab[t] = is64 ? labels_raw[2 * t] : labels_raw[t];
    __syncthreads();
    if (t < 32) {
        int lb = lab[t];
        float best = -2.0f; int bi = 0;
        for (int j = 0; j < 32; j++) {
            float v = (lab[j] != lb) ? uf[t * 32 + j] : -1.0f;
            if (v > best) { best = v; bi = j; }    // first-max ties
        }
        g_negidx[t] = bi;
    }
}

// ---------------- Kernel E: loss terms (warp per (b,i)) ----------------
__global__ void loss_kernel() {
    __shared__ float part[8];
    int wid = threadIdx.x >> 5, lane = threadIdx.x & 31;
    int gw = blockIdx.x * 8 + wid;          // 0..32767
    int b = gw >> 10, i = gw & 1023;
    unsigned long long key = g_arg[gw];
    int idx = (int)(0xFFFFFFFFu - (unsigned int)(key & 0xFFFFFFFFull));
    int nb = g_negidx[b];
    const float4* q  = (const float4*)(g_qgt + (size_t)gw * NC);
    const float4* kp = (const float4*)(g_kgt + ((size_t)b  * NS + idx) * NC);
    const float4* kn = (const float4*)(g_kgt + ((size_t)nb * NS + i)   * NC);
    float dp = 0.f, dn = 0.f;
#pragma unroll
    for (int u = 0; u < 2; u++) {
        int c4 = lane + u * 32;
        float4 qv = q[c4], pv = kp[c4], nv = kn[c4];
        dp += qv.x * pv.x + qv.y * pv.y + qv.z * pv.z + qv.w * pv.w;
        dn += qv.x * nv.x + qv.y * nv.y + qv.z * nv.z + qv.w * nv.w;
    }
#pragma unroll
    for (int off = 16; off; off >>= 1) {
        dp += __shfl_xor_sync(0xFFFFFFFFu, dp, off);
        dn += __shfl_xor_sync(0xFFFFFFFFu, dn, off);
    }
    if (lane == 0) {
        float p = dp * 10.0f;   // / TEMP
        float n = dn * 10.0f;
        part[wid] = logf(expf(p) + expf(n) + 1e-6f) - p;
    }
    __syncthreads();
    if (threadIdx.x == 0) {
        float s = 0.f;
        for (int w = 0; w < 8; w++) s += part[w];
        atomicAdd(&g_loss, s);
    }
}

__global__ void finalize_kernel(float* out) {
    out[0] = g_loss * (1.0f / 32768.0f);   // mean * LAM(=1)
}

// ---------------- entry ----------------
extern "C" void kernel_launch(void* const* d_in, const int* in_sizes, int n_in,
                              void* d_out, int out_size) {
    const float* q_b    = (const float*)d_in[0];
    const float* k_b    = (const float*)d_in[1];
    const float* q_grid = (const float*)d_in[2];
    const float* k_grid = (const float*)d_in[3];
    const int*   labels = (const int*)d_in[4];

    static int smem_set = 0;
    if (!smem_set) {
        cudaFuncSetAttribute(mma_argmax_kernel,
                             cudaFuncAttributeMaxDynamicSharedMemorySize, SMEM_SZ);
        smem_set = 1;
    }

    norms_init_kernel<<<128, 256>>>(k_b, q_grid, k_grid);
    transpose_kernel<<<dim3(32, 8, 128), dim3(32, 8)>>>(q_grid, k_grid, q_b, k_b);
    negidx_kernel<<<1, 1024>>>(labels);
    mma_argmax_kernel<<<dim3(2, 8, 32), 128, SMEM_SZ>>>();
    loss_kernel<<<4096, 256>>>();
    finalize_kernel<<<1, 1>>>((float*)d_out);
}